// round 5
// baseline (speedup 1.0000x reference)
#include <cuda_runtime.h>
#include <cstdint>
#include <cstddef>

#define N_HITS   16384
#define N_EDGES  262144
#define N_GROUPS 512
#define HID      128
#define FFN_DIM  512
#define NLAYERS  3

// ---------------- scratch (static device allocations; no runtime alloc) ----------------
__device__ float    g_h[N_HITS * HID];
__device__ float    g_qkv[N_HITS * 3 * HID];
__device__ float    g_attn[N_HITS * HID];
__device__ float    g_tmp[N_HITS * FFN_DIM];
__device__ int      g_deg[N_HITS];
__device__ int      g_rowptr[N_HITS + 1];
__device__ int      g_cursor[N_HITS];
__device__ int      g_esorted[N_EDGES];
__device__ unsigned g_gmax[N_GROUPS * HID];
__device__ float    g_sum0[N_GROUPS * HID];
__device__ float    g_sum1[N_GROUPS * HID];
__device__ int      g_cnt[3 * N_GROUPS];
__device__ float    g_ge[N_GROUPS * 2 * HID];
__device__ float    g_Aff[N_GROUPS * HID];
__device__ float    g_Bff[N_GROUPS * HID];
__device__ float    g_S[N_GROUPS * N_GROUPS];

// ---------------- packed f32x2 helpers (Blackwell FFMA2 path) ----------------
__device__ __forceinline__ unsigned long long pk2(float lo, float hi) {
    unsigned long long r;
    asm("mov.b64 %0, {%1, %2};" : "=l"(r) : "f"(lo), "f"(hi));
    return r;
}
__device__ __forceinline__ void fma2(unsigned long long& d, unsigned long long a, unsigned long long b) {
    asm("fma.rn.f32x2 %0, %1, %2, %3;" : "=l"(d) : "l"(a), "l"(b), "l"(d));
}
__device__ __forceinline__ float2 upk2(unsigned long long v) {
    float lo, hi;
    asm("mov.b64 {%0, %1}, %2;" : "=f"(lo), "=f"(hi) : "l"(v));
    float2 r; r.x = lo; r.y = hi; return r;
}

// ---------------- init / CSR build ----------------
__global__ void zero_kernel() {
    int i = blockIdx.x * blockDim.x + threadIdx.x;
    int st = gridDim.x * blockDim.x;
    for (int k = i; k < N_HITS; k += st) g_deg[k] = 0;
    for (int k = i; k < N_GROUPS * HID; k += st) {
        g_gmax[k] = 0u; g_sum0[k] = 0.f; g_sum1[k] = 0.f;
    }
    for (int k = i; k < 3 * N_GROUPS; k += st) g_cnt[k] = 0;
}

__global__ void hist_kernel(const int* __restrict__ dst) {
    int e = blockIdx.x * blockDim.x + threadIdx.x;
    if (e < N_EDGES) atomicAdd(&g_deg[dst[e]], 1);
}

__global__ void scan_kernel() {   // 1 block, 1024 threads, 16 items each
    __shared__ int sm[1024];
    int tid = threadIdx.x;
    int base = tid * 16;
    int loc[16]; int run = 0;
#pragma unroll
    for (int t = 0; t < 16; t++) { loc[t] = run; run += g_deg[base + t]; }
    sm[tid] = run;
    __syncthreads();
    for (int off = 1; off < 1024; off <<= 1) {
        int v = (tid >= off) ? sm[tid - off] : 0;
        __syncthreads();
        sm[tid] += v;
        __syncthreads();
    }
    int offs = (tid > 0) ? sm[tid - 1] : 0;
#pragma unroll
    for (int t = 0; t < 16; t++) {
        int rp = offs + loc[t];
        g_rowptr[base + t] = rp;
        g_cursor[base + t] = rp;
    }
    if (tid == 1023) g_rowptr[N_HITS] = sm[1023];
}

__global__ void scatter_kernel(const int* __restrict__ dst) {
    int e = blockIdx.x * blockDim.x + threadIdx.x;
    if (e < N_EDGES) {
        int p = atomicAdd(&g_cursor[dst[e]], 1);
        g_esorted[p] = e;
    }
}

// ---------------- embed: h = x @ W(25x128) + b ----------------
__global__ __launch_bounds__(128) void embed_kernel(const float* __restrict__ x,
                                                    const float* __restrict__ W,
                                                    const float* __restrict__ b) {
    __shared__ float Ws[25 * HID];
    __shared__ float xs[16 * 25];
    int tid = threadIdx.x;
    for (int i = tid; i < 25 * HID; i += 128) Ws[i] = W[i];
    int rowBase = blockIdx.x * 16;
    for (int i = tid; i < 16 * 25; i += 128) xs[i] = x[(size_t)rowBase * 25 + i];
    __syncthreads();
    float bb = b[tid];
    for (int r = 0; r < 16; r++) {
        float acc = bb;
#pragma unroll
        for (int c = 0; c < 25; c++) acc += xs[r * 25 + c] * Ws[c * HID + tid];
        g_h[(size_t)(rowBase + r) * HID + tid] = acc;
    }
}

// ---------------- generic tiled GEMM: C[M,N] = A[M,K]@B[K,N] + bias (opt relu) ----------
// grid = (N/64, M/64), block = 256. lda=K, ldb=N, ldc=N. K % 32 == 0, N % 64 == 0.
__global__ __launch_bounds__(256) void gemm_kernel(const float* __restrict__ A,
                                                   const float* __restrict__ B,
                                                   const float* __restrict__ bias,
                                                   float* __restrict__ C,
                                                   int K, int N, int relu_flag) {
    __shared__ __align__(16) float As[32][68];   // transposed: As[k][row], padded
    __shared__ __align__(16) float Bs[32][64];
    int tid = threadIdx.x;
    int tx = tid & 15, ty = tid >> 4;
    int rowBase = blockIdx.y * 64, colBase = blockIdx.x * 64;
    unsigned long long acc2[4][2];
#pragma unroll
    for (int i = 0; i < 4; i++) { acc2[i][0] = 0ull; acc2[i][1] = 0ull; }
    int a_r = tid >> 3;           // 0..31
    int a_k = (tid & 7) << 2;     // 0..28
    int b_k = tid >> 4;           // 0..15
    int b_c = (tid & 15) << 2;    // 0..60

    for (int kc = 0; kc < K; kc += 32) {
#pragma unroll
        for (int rr = 0; rr < 2; rr++) {
            int r = a_r + rr * 32;
            float4 av = *(const float4*)&A[(size_t)(rowBase + r) * K + kc + a_k];
            As[a_k + 0][r] = av.x; As[a_k + 1][r] = av.y;
            As[a_k + 2][r] = av.z; As[a_k + 3][r] = av.w;
        }
#pragma unroll
        for (int rr = 0; rr < 2; rr++) {
            int kk = b_k + rr * 16;
            *(float4*)&Bs[kk][b_c] = *(const float4*)&B[(size_t)(kc + kk) * N + colBase + b_c];
        }
        __syncthreads();
#pragma unroll
        for (int k = 0; k < 32; k++) {
            float4 a4 = *(const float4*)&As[k][ty << 2];
            const unsigned long long* bp = (const unsigned long long*)&Bs[k][tx << 2];
            unsigned long long b0 = bp[0], b1 = bp[1];
            unsigned long long ad;
            ad = pk2(a4.x, a4.x); fma2(acc2[0][0], ad, b0); fma2(acc2[0][1], ad, b1);
            ad = pk2(a4.y, a4.y); fma2(acc2[1][0], ad, b0); fma2(acc2[1][1], ad, b1);
            ad = pk2(a4.z, a4.z); fma2(acc2[2][0], ad, b0); fma2(acc2[2][1], ad, b1);
            ad = pk2(a4.w, a4.w); fma2(acc2[3][0], ad, b0); fma2(acc2[3][1], ad, b1);
        }
        __syncthreads();
    }
    int col = colBase + (tx << 2);
    float4 bv = {0.f, 0.f, 0.f, 0.f};
    if (bias) { bv.x = bias[col]; bv.y = bias[col + 1]; bv.z = bias[col + 2]; bv.w = bias[col + 3]; }
#pragma unroll
    for (int i = 0; i < 4; i++) {
        float2 v0 = upk2(acc2[i][0]), v1 = upk2(acc2[i][1]);
        float4 o;
        o.x = v0.x + bv.x; o.y = v0.y + bv.y; o.z = v1.x + bv.z; o.w = v1.y + bv.w;
        if (relu_flag) {
            o.x = fmaxf(o.x, 0.f); o.y = fmaxf(o.y, 0.f);
            o.z = fmaxf(o.z, 0.f); o.w = fmaxf(o.w, 0.f);
        }
        int row = rowBase + (ty << 2) + i;
        *(float4*)&C[(size_t)row * N + col] = o;
    }
}

// ---------------- attention: one warp per node, CSR gather + online softmax ------------
// lane covers dims 4*lane..4*lane+3 (head = lane/8); 8-lane xor-reduce for the head logit.
__global__ __launch_bounds__(256) void attn_kernel(const float* __restrict__ qkv,
                                                   const int* __restrict__ src_idx,
                                                   const float* __restrict__ edge_attr,
                                                   const float* __restrict__ We,
                                                   const float* __restrict__ be,
                                                   float* __restrict__ attn) {
    __shared__ float4 We_s[5][32];
    __shared__ float4 be_s[32];
    int tid = threadIdx.x;
    if (tid < 160) { int c = tid >> 5, l = tid & 31; We_s[c][l] = *(const float4*)&We[c * HID + l * 4]; }
    if (tid < 32) be_s[tid] = *(const float4*)&be[tid * 4];
    __syncthreads();
    int lane = tid & 31;
    int node = blockIdx.x * 8 + (tid >> 5);
    if (node >= N_HITS) return;

    float4 q4 = *(const float4*)&qkv[(size_t)node * 384 + lane * 4];
    int p0 = g_rowptr[node], p1 = g_rowptr[node + 1];
    float m = -INFINITY, s = 0.f;
    float ax = 0.f, ay = 0.f, az = 0.f, aw = 0.f;
    float4 be4 = be_s[lane];
    float4 w0 = We_s[0][lane], w1 = We_s[1][lane], w2 = We_s[2][lane],
           w3 = We_s[3][lane], w4 = We_s[4][lane];

    for (int j = p0; j < p1; j++) {
        int eid = g_esorted[j];
        int sn = src_idx[eid];
        const float* ea = edge_attr + (size_t)eid * 5;
        float c0 = ea[0], c1 = ea[1], c2 = ea[2], c3 = ea[3], c4 = ea[4];
        float ex = be4.x + c0 * w0.x + c1 * w1.x + c2 * w2.x + c3 * w3.x + c4 * w4.x;
        float ey = be4.y + c0 * w0.y + c1 * w1.y + c2 * w2.y + c3 * w3.y + c4 * w4.y;
        float ez = be4.z + c0 * w0.z + c1 * w1.z + c2 * w2.z + c3 * w3.z + c4 * w4.z;
        float ew = be4.w + c0 * w0.w + c1 * w1.w + c2 * w2.w + c3 * w3.w + c4 * w4.w;
        const float* kb = qkv + (size_t)sn * 384;
        float4 k4 = *(const float4*)&kb[HID + lane * 4];
        float4 v4 = *(const float4*)&kb[2 * HID + lane * 4];
        float kx = k4.x + ex, ky = k4.y + ey, kz = k4.z + ez, kw = k4.w + ew;
        float prod = q4.x * kx + q4.y * ky + q4.z * kz + q4.w * kw;
        prod += __shfl_xor_sync(0xffffffffu, prod, 1);
        prod += __shfl_xor_sync(0xffffffffu, prod, 2);
        prod += __shfl_xor_sync(0xffffffffu, prod, 4);
        float logit = prod * 0.17677669529663689f;  // 1/sqrt(32)
        float nm = fmaxf(m, logit);
        float corr = __expf(m - nm);
        float p = __expf(logit - nm);
        s = s * corr + p;
        ax = ax * corr + p * (v4.x + ex);
        ay = ay * corr + p * (v4.y + ey);
        az = az * corr + p * (v4.z + ez);
        aw = aw * corr + p * (v4.w + ew);
        m = nm;
    }
    float inv = 1.f / fmaxf(s, 1e-9f);
    float4 o; o.x = ax * inv; o.y = ay * inv; o.z = az * inv; o.w = aw * inv;
    *(float4*)&attn[(size_t)node * HID + lane * 4] = o;
}

// ---------------- residual + LayerNorm (warp per row) ----------------
__global__ __launch_bounds__(256) void ln_res_kernel(float* __restrict__ h,
                                                     const float* __restrict__ delta,
                                                     const float* __restrict__ gamma,
                                                     const float* __restrict__ beta) {
    int lane = threadIdx.x & 31;
    int row = blockIdx.x * 8 + (threadIdx.x >> 5);
    float4 hv = *(const float4*)&h[(size_t)row * HID + lane * 4];
    float4 dv = *(const float4*)&delta[(size_t)row * HID + lane * 4];
    float vx = hv.x + dv.x, vy = hv.y + dv.y, vz = hv.z + dv.z, vw = hv.w + dv.w;
    float sum = vx + vy + vz + vw;
#pragma unroll
    for (int o = 16; o > 0; o >>= 1) sum += __shfl_xor_sync(0xffffffffu, sum, o);
    float mean = sum * (1.f / 128.f);
    float dx = vx - mean, dy = vy - mean, dz = vz - mean, dw = vw - mean;
    float ss = dx * dx + dy * dy + dz * dz + dw * dw;
#pragma unroll
    for (int o = 16; o > 0; o >>= 1) ss += __shfl_xor_sync(0xffffffffu, ss, o);
    float rstd = rsqrtf(ss * (1.f / 128.f) + 1e-5f);
    float4 gv = *(const float4*)&gamma[lane * 4];
    float4 bv = *(const float4*)&beta[lane * 4];
    float4 o4;
    o4.x = dx * rstd * gv.x + bv.x;
    o4.y = dy * rstd * gv.y + bv.y;
    o4.z = dz * rstd * gv.z + bv.z;
    o4.w = dw * rstd * gv.w + bv.w;
    *(float4*)&h[(size_t)row * HID + lane * 4] = o4;
}

// ---------------- group pooling (atomics) ----------------
__global__ void pool_kernel(const float* __restrict__ x, const int* __restrict__ grp,
                            const float* __restrict__ h) {
    int tid = threadIdx.x;
    int hit = blockIdx.x * 2 + (tid >> 7);
    int f = tid & 127;
    int g = grp[hit];
    float val = h[(size_t)hit * HID + f];
    unsigned u = __float_as_uint(val);
    unsigned enc = (u & 0x80000000u) ? ~u : (u | 0x80000000u);
    atomicMax(&g_gmax[g * HID + f], enc);
    int view = (int)x[(size_t)hit * 25 + 3];
    if (view == 0)      atomicAdd(&g_sum0[g * HID + f], val);
    else if (view == 1) atomicAdd(&g_sum1[g * HID + f], val);
    if (f == 0) {
        atomicAdd(&g_cnt[g], 1);
        if (view == 0)      atomicAdd(&g_cnt[N_GROUPS + g], 1);
        else if (view == 1) atomicAdd(&g_cnt[2 * N_GROUPS + g], 1);
    }
}

__global__ void ge_kernel() {
    int g = blockIdx.x, f = threadIdx.x;
    float cA = (float)g_cnt[g];
    float c0 = (float)g_cnt[N_GROUPS + g];
    float c1 = (float)g_cnt[2 * N_GROUPS + g];
    float s0 = g_sum0[g * HID + f], s1 = g_sum1[g * HID + f];
    float px = s0 / fmaxf(c0, 1.f), py = s1 / fmaxf(c1, 1.f);
    float hx = (c0 > 0.f) ? 1.f : 0.f, hy = (c1 > 0.f) ? 1.f : 0.f;
    float sum_feat = px * hx + py * hy;
    float valid = fmaxf(hx + hy, 1.f);
    g_ge[g * 256 + f] = sum_feat / valid;
    unsigned u = g_gmax[g * HID + f];
    float gm = 0.f;
    if (cA > 0.f) {
        unsigned bits = (u & 0x80000000u) ? (u & 0x7fffffffu) : ~u;
        gm = __uint_as_float(bits);
    }
    g_ge[g * 256 + HID + f] = gm;
}

// ---------------- pairwise affinity scores ----------------
__global__ void scores_kernel(const float* __restrict__ W2v, const float* __restrict__ b2v) {
    __shared__ float sA[16][129];
    __shared__ float sB[16][129];
    __shared__ float w2s[HID];
    int tx = threadIdx.x, ty = threadIdx.y;
    int tid = ty * 16 + tx;
    int iBase = blockIdx.y * 16, jBase = blockIdx.x * 16;
#pragma unroll
    for (int q = 0; q < 2; q++) {
        int idx4 = tid * 2 + q;          // 0..511 over 16x128 floats (as float4s)
        int r = idx4 >> 5;
        int c4 = (idx4 & 31) << 2;
        float4 a = *(const float4*)&g_Aff[(size_t)(iBase + r) * HID + c4];
        sA[r][c4] = a.x; sA[r][c4 + 1] = a.y; sA[r][c4 + 2] = a.z; sA[r][c4 + 3] = a.w;
        float4 b = *(const float4*)&g_Bff[(size_t)(jBase + r) * HID + c4];
        sB[r][c4] = b.x; sB[r][c4 + 1] = b.y; sB[r][c4 + 2] = b.z; sB[r][c4 + 3] = b.w;
    }
    if (tid < HID) w2s[tid] = W2v[tid];
    __syncthreads();
    float acc = b2v[0];
#pragma unroll 8
    for (int k = 0; k < HID; k++) {
        float t = sA[ty][k] + sB[tx][k];
        acc += fmaxf(t, 0.f) * w2s[k];
    }
    g_S[(size_t)(iBase + ty) * N_GROUPS + jBase + tx] = acc;
}

__global__ void final_kernel(const int* __restrict__ batch, float* __restrict__ out) {
    int idx = blockIdx.x * blockDim.x + threadIdx.x;
    if (idx >= N_GROUPS * N_GROUPS) return;
    int i = idx >> 9, j = idx & 511;
    float sc = 0.5f * (g_S[(size_t)i * N_GROUPS + j] + g_S[(size_t)j * N_GROUPS + i]);
    float p = 1.f / (1.f + expf(-sc));
    out[idx] = (batch[i] == batch[j]) ? p : 0.f;
}

// ---------------- host launcher ----------------
extern "C" void kernel_launch(void* const* d_in, const int* in_sizes, int n_in,
                              void* d_out, int out_size) {
    const float* x         = (const float*)d_in[0];
    const int*   ei        = (const int*)d_in[1];      // [2, E]: src then dst
    const float* edge_attr = (const float*)d_in[2];
    const int*   grp       = (const int*)d_in[3];
    const int*   batch     = (const int*)d_in[4];
    const float* embed_W   = (const float*)d_in[5];
    const float* embed_b   = (const float*)d_in[6];
    const float* Wqkv      = (const float*)d_in[7];
    const float* bqkv      = (const float*)d_in[8];
    const float* We        = (const float*)d_in[9];
    const float* be        = (const float*)d_in[10];
    const float* Wo        = (const float*)d_in[11];
    const float* bo        = (const float*)d_in[12];
    const float* ln1g      = (const float*)d_in[13];
    const float* ln1b      = (const float*)d_in[14];
    const float* W1        = (const float*)d_in[15];
    const float* b1        = (const float*)d_in[16];
    const float* W2        = (const float*)d_in[17];
    const float* b2        = (const float*)d_in[18];
    const float* ln2g      = (const float*)d_in[19];
    const float* ln2b      = (const float*)d_in[20];
    const float* affW1     = (const float*)d_in[21];
    const float* affb1     = (const float*)d_in[22];
    const float* affW2     = (const float*)d_in[23];
    const float* affb2     = (const float*)d_in[24];
    float* out = (float*)d_out;

    const int* dst = ei + N_EDGES;

    float *h, *qkv, *attn, *tmp, *ge, *Abuf, *Bbuf;
    cudaGetSymbolAddress((void**)&h,    g_h);
    cudaGetSymbolAddress((void**)&qkv,  g_qkv);
    cudaGetSymbolAddress((void**)&attn, g_attn);
    cudaGetSymbolAddress((void**)&tmp,  g_tmp);
    cudaGetSymbolAddress((void**)&ge,   g_ge);
    cudaGetSymbolAddress((void**)&Abuf, g_Aff);
    cudaGetSymbolAddress((void**)&Bbuf, g_Bff);

    // init + CSR (edge_index is layer-invariant: build once per launch)
    zero_kernel<<<128, 256>>>();
    hist_kernel<<<N_EDGES / 256, 256>>>(dst);
    scan_kernel<<<1, 1024>>>();
    scatter_kernel<<<N_EDGES / 256, 256>>>(dst);

    // embed
    embed_kernel<<<N_HITS / 16, 128>>>(x, embed_W, embed_b);

    for (int l = 0; l < NLAYERS; l++) {
        // qkv = h @ Wqkv[l] + bqkv[l]   (16384 x 128 x 384)
        gemm_kernel<<<dim3(384 / 64, N_HITS / 64), 256>>>(
            h, Wqkv + (size_t)l * HID * 3 * HID, bqkv + (size_t)l * 3 * HID,
            qkv, HID, 3 * HID, 0);
        // edge attention
        attn_kernel<<<N_HITS / 8, 256>>>(qkv, ei, edge_attr,
                                         We + (size_t)l * 5 * HID, be + (size_t)l * HID, attn);
        // wo_out = attn @ Wo + bo
        gemm_kernel<<<dim3(HID / 64, N_HITS / 64), 256>>>(
            attn, Wo + (size_t)l * HID * HID, bo + (size_t)l * HID, tmp, HID, HID, 0);
        // h = LN(h + wo_out)
        ln_res_kernel<<<N_HITS / 8, 256>>>(h, tmp, ln1g + (size_t)l * HID, ln1b + (size_t)l * HID);
        // hidden = relu(h @ W1 + b1)
        gemm_kernel<<<dim3(FFN_DIM / 64, N_HITS / 64), 256>>>(
            h, W1 + (size_t)l * HID * FFN_DIM, b1 + (size_t)l * FFN_DIM, tmp, HID, FFN_DIM, 1);
        // ffn_out = hidden @ W2 + b2
        gemm_kernel<<<dim3(HID / 64, N_HITS / 64), 256>>>(
            tmp, W2 + (size_t)l * FFN_DIM * HID, b2 + (size_t)l * HID, attn, FFN_DIM, HID, 0);
        // h = LN(h + ffn_out)
        ln_res_kernel<<<N_HITS / 8, 256>>>(h, attn, ln2g + (size_t)l * HID, ln2b + (size_t)l * HID);
    }

    // group pooling + ge features
    pool_kernel<<<N_HITS / 2, 256>>>(x, grp, h);
    ge_kernel<<<N_GROUPS, HID>>>();

    // A = ge @ W1a + b1 ; B = ge @ W1b    (512 x 256 x 128)
    gemm_kernel<<<dim3(HID / 64, N_GROUPS / 64), 256>>>(ge, affW1, affb1, Abuf, 2 * HID, HID, 0);
    gemm_kernel<<<dim3(HID / 64, N_GROUPS / 64), 256>>>(ge, affW1 + (size_t)2 * HID * HID, nullptr,
                                                        Bbuf, 2 * HID, HID, 0);

    // pairwise scores + symmetrize + sigmoid + event mask
    scores_kernel<<<dim3(N_GROUPS / 16, N_GROUPS / 16), dim3(16, 16)>>>(affW2, affb2);
    final_kernel<<<(N_GROUPS * N_GROUPS) / 256, 256>>>(batch, out);

    (void)in_sizes; (void)n_in; (void)out_size;
}

// round 6
// speedup vs baseline: 1.3851x; 1.3851x over previous
#include <cuda_runtime.h>
#include <cuda_bf16.h>
#include <cstdint>
#include <cstddef>

#define N_HITS   16384
#define N_EDGES  262144
#define N_GROUPS 512
#define HID      128
#define FFN_DIM  512
#define NLAYERS  3

// ---------------- scratch (static device allocations; no runtime alloc) ----------------
__device__ float    g_h[N_HITS * HID];
__device__ float    g_qkv[N_HITS * 3 * HID];
__device__ float    g_attn[N_HITS * HID];
__device__ float    g_tmp[N_HITS * FFN_DIM];
__device__ int      g_deg[N_HITS];
__device__ int      g_rowptr[N_HITS + 1];
__device__ int      g_cursor[N_HITS];
__device__ int      g_esorted[N_EDGES];
__device__ unsigned g_gmax[N_GROUPS * HID];
__device__ float    g_sum0[N_GROUPS * HID];
__device__ float    g_sum1[N_GROUPS * HID];
__device__ int      g_cnt[3 * N_GROUPS];
__device__ float    g_ge[N_GROUPS * 2 * HID];
__device__ float    g_Aff[N_GROUPS * HID];
__device__ float    g_Bff[N_GROUPS * HID];
__device__ float    g_S[N_GROUPS * N_GROUPS];

// ---------------- bf16 split helpers ----------------
__device__ __forceinline__ uint32_t bf2_hi_lo(float x, float y, uint32_t& lo_out) {
    __nv_bfloat16 hx = __float2bfloat16(x);
    __nv_bfloat16 hy = __float2bfloat16(y);
    float rx = x - __bfloat162float(hx);
    float ry = y - __bfloat162float(hy);
    __nv_bfloat16 lx = __float2bfloat16(rx);
    __nv_bfloat16 ly = __float2bfloat16(ry);
    lo_out = (uint32_t)__bfloat16_as_ushort(lx) | ((uint32_t)__bfloat16_as_ushort(ly) << 16);
    return (uint32_t)__bfloat16_as_ushort(hx) | ((uint32_t)__bfloat16_as_ushort(hy) << 16);
}

__device__ __forceinline__ void mma16816(float* c, const uint32_t* a, const uint32_t* b) {
    asm volatile(
        "mma.sync.aligned.m16n8k16.row.col.f32.bf16.bf16.f32 "
        "{%0,%1,%2,%3}, {%4,%5,%6,%7}, {%8,%9}, {%0,%1,%2,%3};"
        : "+f"(c[0]), "+f"(c[1]), "+f"(c[2]), "+f"(c[3])
        : "r"(a[0]), "r"(a[1]), "r"(a[2]), "r"(a[3]), "r"(b[0]), "r"(b[1]));
}

// ---------------- init / CSR build ----------------
__global__ void zero_kernel() {
    int i = blockIdx.x * blockDim.x + threadIdx.x;
    int st = gridDim.x * blockDim.x;
    for (int k = i; k < N_HITS; k += st) g_deg[k] = 0;
    for (int k = i; k < N_GROUPS * HID; k += st) {
        g_gmax[k] = 0u; g_sum0[k] = 0.f; g_sum1[k] = 0.f;
    }
    for (int k = i; k < 3 * N_GROUPS; k += st) g_cnt[k] = 0;
}

__global__ void hist_kernel(const int* __restrict__ dst) {
    int e = blockIdx.x * blockDim.x + threadIdx.x;
    if (e < N_EDGES) atomicAdd(&g_deg[dst[e]], 1);
}

__global__ void scan_kernel() {   // 1 block, 1024 threads, 16 items each
    __shared__ int sm[1024];
    int tid = threadIdx.x;
    int base = tid * 16;
    int loc[16]; int run = 0;
#pragma unroll
    for (int t = 0; t < 16; t++) { loc[t] = run; run += g_deg[base + t]; }
    sm[tid] = run;
    __syncthreads();
    for (int off = 1; off < 1024; off <<= 1) {
        int v = (tid >= off) ? sm[tid - off] : 0;
        __syncthreads();
        sm[tid] += v;
        __syncthreads();
    }
    int offs = (tid > 0) ? sm[tid - 1] : 0;
#pragma unroll
    for (int t = 0; t < 16; t++) {
        int rp = offs + loc[t];
        g_rowptr[base + t] = rp;
        g_cursor[base + t] = rp;
    }
    if (tid == 1023) g_rowptr[N_HITS] = sm[1023];
}

__global__ void scatter_kernel(const int* __restrict__ dst) {
    int e = blockIdx.x * blockDim.x + threadIdx.x;
    if (e < N_EDGES) {
        int p = atomicAdd(&g_cursor[dst[e]], 1);
        g_esorted[p] = e;
    }
}

// ---------------- embed: h = x @ W(25x128) + b ----------------
__global__ __launch_bounds__(128) void embed_kernel(const float* __restrict__ x,
                                                    const float* __restrict__ W,
                                                    const float* __restrict__ b) {
    __shared__ float Ws[25 * HID];
    __shared__ float xs[16 * 25];
    int tid = threadIdx.x;
    for (int i = tid; i < 25 * HID; i += 128) Ws[i] = W[i];
    int rowBase = blockIdx.x * 16;
    for (int i = tid; i < 16 * 25; i += 128) xs[i] = x[(size_t)rowBase * 25 + i];
    __syncthreads();
    float bb = b[tid];
    for (int r = 0; r < 16; r++) {
        float acc = bb;
#pragma unroll
        for (int c = 0; c < 25; c++) acc += xs[r * 25 + c] * Ws[c * HID + tid];
        g_h[(size_t)(rowBase + r) * HID + tid] = acc;
    }
}

// ---------------- tensor-core GEMM: C[M,N] = A[M,K]@B[K,N] + bias (opt relu) ----------
// 3-term bf16 split for fp32-level accuracy on HMMA.
// grid = (N/64, M/128), block = 256 (8 warps, warp tile 32x32). K % 32 == 0.
#define AST 20   // As row stride (uint32 words): conflict-free fragment loads
#define BST 17   // Bs row stride: conflict-free staging stores

__global__ __launch_bounds__(256) void gemm_tc(const float* __restrict__ A,
                                               const float* __restrict__ B,
                                               const float* __restrict__ bias,
                                               float* __restrict__ C,
                                               int K, int N, int relu_flag) {
    __shared__ uint32_t Ah[128 * AST], Al[128 * AST];
    __shared__ uint32_t Bh[64 * BST],  Bl[64 * BST];
    int tid  = threadIdx.x;
    int lane = tid & 31, warp = tid >> 5;
    int wm = (warp & 3) * 32;       // M offset of warp tile
    int wn = (warp >> 2) * 32;      // N offset of warp tile
    int g = lane >> 2, t4 = lane & 3;
    int rowBase = blockIdx.y * 128, colBase = blockIdx.x * 64;

    float acc[2][4][4];
#pragma unroll
    for (int mf = 0; mf < 2; mf++)
#pragma unroll
        for (int nf = 0; nf < 4; nf++)
#pragma unroll
            for (int q = 0; q < 4; q++) acc[mf][nf][q] = 0.f;

    int arow = tid >> 4;        // 0..15
    int akp  = tid & 15;        // k-pair within chunk
    int bn   = tid & 63;
    int bk0  = tid >> 6;        // 0..3

    for (int kc = 0; kc < K; kc += 32) {
        // stage A (128 x 32) as bf16 hi/lo pairs
#pragma unroll
        for (int p = 0; p < 8; p++) {
            int r = p * 16 + arow;
            float2 v = *(const float2*)&A[(size_t)(rowBase + r) * K + kc + 2 * akp];
            uint32_t lo;
            uint32_t hi = bf2_hi_lo(v.x, v.y, lo);
            Ah[r * AST + akp] = hi;
            Al[r * AST + akp] = lo;
        }
        // stage B (32 x 64) column-packed: Bs[n][kpair] = {B[k][n], B[k+1][n]}
#pragma unroll
        for (int p = 0; p < 4; p++) {
            int kpr = p * 4 + bk0;
            float x0 = B[(size_t)(kc + 2 * kpr) * N + colBase + bn];
            float x1 = B[(size_t)(kc + 2 * kpr + 1) * N + colBase + bn];
            uint32_t lo;
            uint32_t hi = bf2_hi_lo(x0, x1, lo);
            Bh[bn * BST + kpr] = hi;
            Bl[bn * BST + kpr] = lo;
        }
        __syncthreads();

#pragma unroll
        for (int ks = 0; ks < 2; ks++) {
            uint32_t ah[2][4], al[2][4], bh[4][2], bl[4][2];
            int ci = ks * 8 + t4;
#pragma unroll
            for (int mf = 0; mf < 2; mf++) {
                int r0 = (wm + mf * 16 + g) * AST;
                ah[mf][0] = Ah[r0 + ci];           ah[mf][1] = Ah[r0 + 8 * AST + ci];
                ah[mf][2] = Ah[r0 + ci + 4];       ah[mf][3] = Ah[r0 + 8 * AST + ci + 4];
                al[mf][0] = Al[r0 + ci];           al[mf][1] = Al[r0 + 8 * AST + ci];
                al[mf][2] = Al[r0 + ci + 4];       al[mf][3] = Al[r0 + 8 * AST + ci + 4];
            }
#pragma unroll
            for (int nf = 0; nf < 4; nf++) {
                int c0 = (wn + nf * 8 + g) * BST;
                bh[nf][0] = Bh[c0 + ci];  bh[nf][1] = Bh[c0 + ci + 4];
                bl[nf][0] = Bl[c0 + ci];  bl[nf][1] = Bl[c0 + ci + 4];
            }
            // term 1: a_hi * b_hi
#pragma unroll
            for (int mf = 0; mf < 2; mf++)
#pragma unroll
                for (int nf = 0; nf < 4; nf++) mma16816(acc[mf][nf], ah[mf], bh[nf]);
            // term 2: a_lo * b_hi
#pragma unroll
            for (int mf = 0; mf < 2; mf++)
#pragma unroll
                for (int nf = 0; nf < 4; nf++) mma16816(acc[mf][nf], al[mf], bh[nf]);
            // term 3: a_hi * b_lo
#pragma unroll
            for (int mf = 0; mf < 2; mf++)
#pragma unroll
                for (int nf = 0; nf < 4; nf++) mma16816(acc[mf][nf], ah[mf], bl[nf]);
        }
        __syncthreads();
    }

    // epilogue
#pragma unroll
    for (int mf = 0; mf < 2; mf++) {
#pragma unroll
        for (int nf = 0; nf < 4; nf++) {
            int row0 = rowBase + wm + mf * 16 + g;
            int col  = colBase + wn + nf * 8 + 2 * t4;
            float bx = bias ? bias[col] : 0.f;
            float by = bias ? bias[col + 1] : 0.f;
            float v0 = acc[mf][nf][0] + bx, v1 = acc[mf][nf][1] + by;
            float v2 = acc[mf][nf][2] + bx, v3 = acc[mf][nf][3] + by;
            if (relu_flag) {
                v0 = fmaxf(v0, 0.f); v1 = fmaxf(v1, 0.f);
                v2 = fmaxf(v2, 0.f); v3 = fmaxf(v3, 0.f);
            }
            float2 o0; o0.x = v0; o0.y = v1;
            float2 o1; o1.x = v2; o1.y = v3;
            *(float2*)&C[(size_t)row0 * N + col]       = o0;
            *(float2*)&C[(size_t)(row0 + 8) * N + col] = o1;
        }
    }
}

// ---------------- attention: one warp per node, CSR gather + online softmax ------------
__global__ __launch_bounds__(256) void attn_kernel(const float* __restrict__ qkv,
                                                   const int* __restrict__ src_idx,
                                                   const float* __restrict__ edge_attr,
                                                   const float* __restrict__ We,
                                                   const float* __restrict__ be,
                                                   float* __restrict__ attn) {
    __shared__ float4 We_s[5][32];
    __shared__ float4 be_s[32];
    int tid = threadIdx.x;
    if (tid < 160) { int c = tid >> 5, l = tid & 31; We_s[c][l] = *(const float4*)&We[c * HID + l * 4]; }
    if (tid < 32) be_s[tid] = *(const float4*)&be[tid * 4];
    __syncthreads();
    int lane = tid & 31;
    int node = blockIdx.x * 8 + (tid >> 5);
    if (node >= N_HITS) return;

    float4 q4 = *(const float4*)&qkv[(size_t)node * 384 + lane * 4];
    int p0 = g_rowptr[node], p1 = g_rowptr[node + 1];
    float m = -INFINITY, s = 0.f;
    float ax = 0.f, ay = 0.f, az = 0.f, aw = 0.f;
    float4 be4 = be_s[lane];
    float4 w0 = We_s[0][lane], w1 = We_s[1][lane], w2 = We_s[2][lane],
           w3 = We_s[3][lane], w4 = We_s[4][lane];

    for (int j = p0; j < p1; j++) {
        int eid = g_esorted[j];
        int sn = src_idx[eid];
        const float* ea = edge_attr + (size_t)eid * 5;
        float c0 = ea[0], c1 = ea[1], c2 = ea[2], c3 = ea[3], c4 = ea[4];
        float ex = be4.x + c0 * w0.x + c1 * w1.x + c2 * w2.x + c3 * w3.x + c4 * w4.x;
        float ey = be4.y + c0 * w0.y + c1 * w1.y + c2 * w2.y + c3 * w3.y + c4 * w4.y;
        float ez = be4.z + c0 * w0.z + c1 * w1.z + c2 * w2.z + c3 * w3.z + c4 * w4.z;
        float ew = be4.w + c0 * w0.w + c1 * w1.w + c2 * w2.w + c3 * w3.w + c4 * w4.w;
        const float* kb = qkv + (size_t)sn * 384;
        float4 k4 = *(const float4*)&kb[HID + lane * 4];
        float4 v4 = *(const float4*)&kb[2 * HID + lane * 4];
        float kx = k4.x + ex, ky = k4.y + ey, kz = k4.z + ez, kw = k4.w + ew;
        float prod = q4.x * kx + q4.y * ky + q4.z * kz + q4.w * kw;
        prod += __shfl_xor_sync(0xffffffffu, prod, 1);
        prod += __shfl_xor_sync(0xffffffffu, prod, 2);
        prod += __shfl_xor_sync(0xffffffffu, prod, 4);
        float logit = prod * 0.17677669529663689f;  // 1/sqrt(32)
        float nm = fmaxf(m, logit);
        float corr = __expf(m - nm);
        float p = __expf(logit - nm);
        s = s * corr + p;
        ax = ax * corr + p * (v4.x + ex);
        ay = ay * corr + p * (v4.y + ey);
        az = az * corr + p * (v4.z + ez);
        aw = aw * corr + p * (v4.w + ew);
        m = nm;
    }
    float inv = 1.f / fmaxf(s, 1e-9f);
    float4 o; o.x = ax * inv; o.y = ay * inv; o.z = az * inv; o.w = aw * inv;
    *(float4*)&attn[(size_t)node * HID + lane * 4] = o;
}

// ---------------- residual + LayerNorm (warp per row) ----------------
__global__ __launch_bounds__(256) void ln_res_kernel(float* __restrict__ h,
                                                     const float* __restrict__ delta,
                                                     const float* __restrict__ gamma,
                                                     const float* __restrict__ beta) {
    int lane = threadIdx.x & 31;
    int row = blockIdx.x * 8 + (threadIdx.x >> 5);
    float4 hv = *(const float4*)&h[(size_t)row * HID + lane * 4];
    float4 dv = *(const float4*)&delta[(size_t)row * HID + lane * 4];
    float vx = hv.x + dv.x, vy = hv.y + dv.y, vz = hv.z + dv.z, vw = hv.w + dv.w;
    float sum = vx + vy + vz + vw;
#pragma unroll
    for (int o = 16; o > 0; o >>= 1) sum += __shfl_xor_sync(0xffffffffu, sum, o);
    float mean = sum * (1.f / 128.f);
    float dx = vx - mean, dy = vy - mean, dz = vz - mean, dw = vw - mean;
    float ss = dx * dx + dy * dy + dz * dz + dw * dw;
#pragma unroll
    for (int o = 16; o > 0; o >>= 1) ss += __shfl_xor_sync(0xffffffffu, ss, o);
    float rstd = rsqrtf(ss * (1.f / 128.f) + 1e-5f);
    float4 gv = *(const float4*)&gamma[lane * 4];
    float4 bv = *(const float4*)&beta[lane * 4];
    float4 o4;
    o4.x = dx * rstd * gv.x + bv.x;
    o4.y = dy * rstd * gv.y + bv.y;
    o4.z = dz * rstd * gv.z + bv.z;
    o4.w = dw * rstd * gv.w + bv.w;
    *(float4*)&h[(size_t)row * HID + lane * 4] = o4;
}

// ---------------- group pooling (atomics) ----------------
__global__ void pool_kernel(const float* __restrict__ x, const int* __restrict__ grp,
                            const float* __restrict__ h) {
    int tid = threadIdx.x;
    int hit = blockIdx.x * 2 + (tid >> 7);
    int f = tid & 127;
    int g = grp[hit];
    float val = h[(size_t)hit * HID + f];
    unsigned u = __float_as_uint(val);
    unsigned enc = (u & 0x80000000u) ? ~u : (u | 0x80000000u);
    atomicMax(&g_gmax[g * HID + f], enc);
    int view = (int)x[(size_t)hit * 25 + 3];
    if (view == 0)      atomicAdd(&g_sum0[g * HID + f], val);
    else if (view == 1) atomicAdd(&g_sum1[g * HID + f], val);
    if (f == 0) {
        atomicAdd(&g_cnt[g], 1);
        if (view == 0)      atomicAdd(&g_cnt[N_GROUPS + g], 1);
        else if (view == 1) atomicAdd(&g_cnt[2 * N_GROUPS + g], 1);
    }
}

__global__ void ge_kernel() {
    int g = blockIdx.x, f = threadIdx.x;
    float cA = (float)g_cnt[g];
    float c0 = (float)g_cnt[N_GROUPS + g];
    float c1 = (float)g_cnt[2 * N_GROUPS + g];
    float s0 = g_sum0[g * HID + f], s1 = g_sum1[g * HID + f];
    float px = s0 / fmaxf(c0, 1.f), py = s1 / fmaxf(c1, 1.f);
    float hx = (c0 > 0.f) ? 1.f : 0.f, hy = (c1 > 0.f) ? 1.f : 0.f;
    float sum_feat = px * hx + py * hy;
    float valid = fmaxf(hx + hy, 1.f);
    g_ge[g * 256 + f] = sum_feat / valid;
    unsigned u = g_gmax[g * HID + f];
    float gm = 0.f;
    if (cA > 0.f) {
        unsigned bits = (u & 0x80000000u) ? (u & 0x7fffffffu) : ~u;
        gm = __uint_as_float(bits);
    }
    g_ge[g * 256 + HID + f] = gm;
}

// ---------------- pairwise affinity scores ----------------
__global__ void scores_kernel(const float* __restrict__ W2v, const float* __restrict__ b2v) {
    __shared__ float sA[16][129];
    __shared__ float sB[16][129];
    __shared__ float w2s[HID];
    int tx = threadIdx.x, ty = threadIdx.y;
    int tid = ty * 16 + tx;
    int iBase = blockIdx.y * 16, jBase = blockIdx.x * 16;
#pragma unroll
    for (int q = 0; q < 2; q++) {
        int idx4 = tid * 2 + q;
        int r = idx4 >> 5;
        int c4 = (idx4 & 31) << 2;
        float4 a = *(const float4*)&g_Aff[(size_t)(iBase + r) * HID + c4];
        sA[r][c4] = a.x; sA[r][c4 + 1] = a.y; sA[r][c4 + 2] = a.z; sA[r][c4 + 3] = a.w;
        float4 b = *(const float4*)&g_Bff[(size_t)(jBase + r) * HID + c4];
        sB[r][c4] = b.x; sB[r][c4 + 1] = b.y; sB[r][c4 + 2] = b.z; sB[r][c4 + 3] = b.w;
    }
    if (tid < HID) w2s[tid] = W2v[tid];
    __syncthreads();
    float acc = b2v[0];
#pragma unroll 8
    for (int k = 0; k < HID; k++) {
        float t = sA[ty][k] + sB[tx][k];
        acc += fmaxf(t, 0.f) * w2s[k];
    }
    g_S[(size_t)(iBase + ty) * N_GROUPS + jBase + tx] = acc;
}

__global__ void final_kernel(const int* __restrict__ batch, float* __restrict__ out) {
    int idx = blockIdx.x * blockDim.x + threadIdx.x;
    if (idx >= N_GROUPS * N_GROUPS) return;
    int i = idx >> 9, j = idx & 511;
    float sc = 0.5f * (g_S[(size_t)i * N_GROUPS + j] + g_S[(size_t)j * N_GROUPS + i]);
    float p = 1.f / (1.f + expf(-sc));
    out[idx] = (batch[i] == batch[j]) ? p : 0.f;
}

// ---------------- host launcher ----------------
extern "C" void kernel_launch(void* const* d_in, const int* in_sizes, int n_in,
                              void* d_out, int out_size) {
    const float* x         = (const float*)d_in[0];
    const int*   ei        = (const int*)d_in[1];      // [2, E]: src then dst
    const float* edge_attr = (const float*)d_in[2];
    const int*   grp       = (const int*)d_in[3];
    const int*   batch     = (const int*)d_in[4];
    const float* embed_W   = (const float*)d_in[5];
    const float* embed_b   = (const float*)d_in[6];
    const float* Wqkv      = (const float*)d_in[7];
    const float* bqkv      = (const float*)d_in[8];
    const float* We        = (const float*)d_in[9];
    const float* be        = (const float*)d_in[10];
    const float* Wo        = (const float*)d_in[11];
    const float* bo        = (const float*)d_in[12];
    const float* ln1g      = (const float*)d_in[13];
    const float* ln1b      = (const float*)d_in[14];
    const float* W1        = (const float*)d_in[15];
    const float* b1        = (const float*)d_in[16];
    const float* W2        = (const float*)d_in[17];
    const float* b2        = (const float*)d_in[18];
    const float* ln2g      = (const float*)d_in[19];
    const float* ln2b      = (const float*)d_in[20];
    const float* affW1     = (const float*)d_in[21];
    const float* affb1     = (const float*)d_in[22];
    const float* affW2     = (const float*)d_in[23];
    const float* affb2     = (const float*)d_in[24];
    float* out = (float*)d_out;

    const int* dst = ei + N_EDGES;

    float *h, *qkv, *attn, *tmp, *ge, *Abuf, *Bbuf;
    cudaGetSymbolAddress((void**)&h,    g_h);
    cudaGetSymbolAddress((void**)&qkv,  g_qkv);
    cudaGetSymbolAddress((void**)&attn, g_attn);
    cudaGetSymbolAddress((void**)&tmp,  g_tmp);
    cudaGetSymbolAddress((void**)&ge,   g_ge);
    cudaGetSymbolAddress((void**)&Abuf, g_Aff);
    cudaGetSymbolAddress((void**)&Bbuf, g_Bff);

    // init + CSR (edge_index is layer-invariant: build once per launch)
    zero_kernel<<<128, 256>>>();
    hist_kernel<<<N_EDGES / 256, 256>>>(dst);
    scan_kernel<<<1, 1024>>>();
    scatter_kernel<<<N_EDGES / 256, 256>>>(dst);

    // embed
    embed_kernel<<<N_HITS / 16, 128>>>(x, embed_W, embed_b);

    for (int l = 0; l < NLAYERS; l++) {
        // qkv = h @ Wqkv[l] + bqkv[l]   (16384 x 128 x 384)
        gemm_tc<<<dim3(384 / 64, N_HITS / 128), 256>>>(
            h, Wqkv + (size_t)l * HID * 3 * HID, bqkv + (size_t)l * 3 * HID,
            qkv, HID, 3 * HID, 0);
        // edge attention
        attn_kernel<<<N_HITS / 8, 256>>>(qkv, ei, edge_attr,
                                         We + (size_t)l * 5 * HID, be + (size_t)l * HID, attn);
        // wo_out = attn @ Wo + bo
        gemm_tc<<<dim3(HID / 64, N_HITS / 128), 256>>>(
            attn, Wo + (size_t)l * HID * HID, bo + (size_t)l * HID, tmp, HID, HID, 0);
        // h = LN(h + wo_out)
        ln_res_kernel<<<N_HITS / 8, 256>>>(h, tmp, ln1g + (size_t)l * HID, ln1b + (size_t)l * HID);
        // hidden = relu(h @ W1 + b1)
        gemm_tc<<<dim3(FFN_DIM / 64, N_HITS / 128), 256>>>(
            h, W1 + (size_t)l * HID * FFN_DIM, b1 + (size_t)l * FFN_DIM, tmp, HID, FFN_DIM, 1);
        // ffn_out = hidden @ W2 + b2
        gemm_tc<<<dim3(HID / 64, N_HITS / 128), 256>>>(
            tmp, W2 + (size_t)l * FFN_DIM * HID, b2 + (size_t)l * HID, attn, FFN_DIM, HID, 0);
        // h = LN(h + ffn_out)
        ln_res_kernel<<<N_HITS / 8, 256>>>(h, attn, ln2g + (size_t)l * HID, ln2b + (size_t)l * HID);
    }

    // group pooling + ge features
    pool_kernel<<<N_HITS / 2, 256>>>(x, grp, h);
    ge_kernel<<<N_GROUPS, HID>>>();

    // A = ge @ W1a + b1 ; B = ge @ W1b    (512 x 256 x 128)
    gemm_tc<<<dim3(HID / 64, N_GROUPS / 128), 256>>>(ge, affW1, affb1, Abuf, 2 * HID, HID, 0);
    gemm_tc<<<dim3(HID / 64, N_GROUPS / 128), 256>>>(ge, affW1 + (size_t)2 * HID * HID, nullptr,
                                                     Bbuf, 2 * HID, HID, 0);

    // pairwise scores + symmetrize + sigmoid + event mask
    scores_kernel<<<dim3(N_GROUPS / 16, N_GROUPS / 16), dim3(16, 16)>>>(affW2, affb2);
    final_kernel<<<(N_GROUPS * N_GROUPS) / 256, 256>>>(batch, out);

    (void)in_sizes; (void)n_in; (void)out_size;
}

// round 7
// speedup vs baseline: 1.4019x; 1.0121x over previous
#include <cuda_runtime.h>
#include <cuda_bf16.h>
#include <cstdint>
#include <cstddef>

#define N_HITS   16384
#define N_EDGES  262144
#define N_GROUPS 512
#define HID      128
#define FFN_DIM  512
#define NLAYERS  3

// ---------------- scratch (static device allocations; no runtime alloc) ----------------
__device__ float    g_h[N_HITS * HID];
__device__ float    g_qkv[N_HITS * 3 * HID];
__device__ float    g_tmp[N_HITS * FFN_DIM];
__device__ uint32_t g_hpk[N_HITS * HID];        // packed bf16 hi/lo of h
__device__ uint32_t g_attnpk[N_HITS * HID];     // packed attn output
__device__ uint32_t g_tmppk[N_HITS * FFN_DIM];  // packed relu(FFN1) hidden
__device__ uint32_t g_gepk[N_GROUPS * 2 * HID];
__device__ uint32_t g_wpk[655360];              // packed weight arena
__device__ int      g_deg[N_HITS];
__device__ int      g_rowptr[N_HITS + 1];
__device__ int      g_cursor[N_HITS];
__device__ int      g_esorted[N_EDGES];
__device__ unsigned g_gmax[N_GROUPS * HID];
__device__ float    g_sum0[N_GROUPS * HID];
__device__ float    g_sum1[N_GROUPS * HID];
__device__ int      g_cnt[3 * N_GROUPS];
__device__ float    g_ge[N_GROUPS * 2 * HID];
__device__ float    g_Aff[N_GROUPS * HID];
__device__ float    g_Bff[N_GROUPS * HID];
__device__ float    g_S[N_GROUPS * N_GROUPS];

// weight arena offsets (u32):
//  per layer l (base = l*196608):
//    qkv_h +0        qkv_l +24576   (N=384,K2=64)
//    wo_h  +49152    wo_l  +57344   (N=128,K2=64)
//    w1_h  +65536    w1_l  +98304   (N=512,K2=64)
//    w2_h  +131072   w2_l  +163840  (N=128,K2=256)
//  aff (base 589824): a_h +0, a_l +16384, b_h +32768, b_l +49152 (N=128,K2=128)
#define WL_STRIDE 196608
#define W_AFF     589824

// ---------------- bf16 split helpers ----------------
__device__ __forceinline__ uint32_t bf2_hi_lo(float x, float y, uint32_t& lo_out) {
    __nv_bfloat16 hx = __float2bfloat16(x);
    __nv_bfloat16 hy = __float2bfloat16(y);
    float rx = x - __bfloat162float(hx);
    float ry = y - __bfloat162float(hy);
    __nv_bfloat16 lx = __float2bfloat16(rx);
    __nv_bfloat16 ly = __float2bfloat16(ry);
    lo_out = (uint32_t)__bfloat16_as_ushort(lx) | ((uint32_t)__bfloat16_as_ushort(ly) << 16);
    return (uint32_t)__bfloat16_as_ushort(hx) | ((uint32_t)__bfloat16_as_ushort(hy) << 16);
}

__device__ __forceinline__ void mma16816(float* c, const uint32_t* a, const uint32_t* b) {
    asm volatile(
        "mma.sync.aligned.m16n8k16.row.col.f32.bf16.bf16.f32 "
        "{%0,%1,%2,%3}, {%4,%5,%6,%7}, {%8,%9}, {%0,%1,%2,%3};"
        : "+f"(c[0]), "+f"(c[1]), "+f"(c[2]), "+f"(c[3])
        : "r"(a[0]), "r"(a[1]), "r"(a[2]), "r"(a[3]), "r"(b[0]), "r"(b[1]));
}

// ---------------- weight packing: B[K][N] fp32 -> Bh/Bl [N][K/2] u32 ----------------
__global__ void pack_weights(const float* __restrict__ Wqkv, const float* __restrict__ Wo,
                             const float* __restrict__ W1, const float* __restrict__ W2,
                             const float* __restrict__ affW1) {
    int i = blockIdx.x * 256 + threadIdx.x;
    if (i >= 327680) return;
    const float* B; int N, K2; uint32_t *oh, *ol; int j;
    if (i < 294912) {
        int l = i / 98304; j = i % 98304;
        size_t base = (size_t)l * WL_STRIDE;
        if (j < 24576)      { B = Wqkv + (size_t)l * 49152; N = 384; K2 = 64;
                              oh = g_wpk + base;          ol = oh + 24576; }
        else if (j < 32768) { j -= 24576; B = Wo + (size_t)l * 16384; N = 128; K2 = 64;
                              oh = g_wpk + base + 49152;  ol = oh + 8192; }
        else if (j < 65536) { j -= 32768; B = W1 + (size_t)l * 65536; N = 512; K2 = 64;
                              oh = g_wpk + base + 65536;  ol = oh + 32768; }
        else                { j -= 65536; B = W2 + (size_t)l * 65536; N = 128; K2 = 256;
                              oh = g_wpk + base + 131072; ol = oh + 32768; }
    } else {
        j = i - 294912;
        if (j < 16384) { B = affW1;                N = 128; K2 = 128;
                         oh = g_wpk + W_AFF;          ol = oh + 16384; }
        else           { j -= 16384; B = affW1 + 32768; N = 128; K2 = 128;
                         oh = g_wpk + W_AFF + 32768;  ol = oh + 16384; }
    }
    int n = j / K2, kp = j % K2;
    float x0 = B[(size_t)(2 * kp) * N + n];
    float x1 = B[(size_t)(2 * kp + 1) * N + n];
    uint32_t lo; uint32_t hi = bf2_hi_lo(x0, x1, lo);
    oh[(size_t)n * K2 + kp] = hi;
    ol[(size_t)n * K2 + kp] = lo;
}

// ---------------- activation packing: src[M][K] fp32 -> dst[M][K] u32 (hi | lo halves) ----
__global__ void pack_rows(const float* __restrict__ src, uint32_t* __restrict__ dst,
                          int K, int total /* M*K/2 */) {
    int i = blockIdx.x * 256 + threadIdx.x;
    if (i >= total) return;
    int K2 = K >> 1;
    int r = i / K2, kp = i % K2;
    float2 v = *(const float2*)&src[(size_t)r * K + 2 * kp];
    uint32_t lo; uint32_t hi = bf2_hi_lo(v.x, v.y, lo);
    dst[(size_t)r * K + kp] = hi;
    dst[(size_t)r * K + K2 + kp] = lo;
}

// ---------------- init / CSR build ----------------
__global__ void zero_kernel() {
    int i = blockIdx.x * blockDim.x + threadIdx.x;
    int st = gridDim.x * blockDim.x;
    for (int k = i; k < N_HITS; k += st) g_deg[k] = 0;
    for (int k = i; k < N_GROUPS * HID; k += st) {
        g_gmax[k] = 0u; g_sum0[k] = 0.f; g_sum1[k] = 0.f;
    }
    for (int k = i; k < 3 * N_GROUPS; k += st) g_cnt[k] = 0;
}

__global__ void hist_kernel(const int* __restrict__ dst) {
    int e = blockIdx.x * blockDim.x + threadIdx.x;
    if (e < N_EDGES) atomicAdd(&g_deg[dst[e]], 1);
}

__global__ void scan_kernel() {   // 1 block, 1024 threads, 16 items each
    __shared__ int sm[1024];
    int tid = threadIdx.x;
    int base = tid * 16;
    int loc[16]; int run = 0;
#pragma unroll
    for (int t = 0; t < 16; t++) { loc[t] = run; run += g_deg[base + t]; }
    sm[tid] = run;
    __syncthreads();
    for (int off = 1; off < 1024; off <<= 1) {
        int v = (tid >= off) ? sm[tid - off] : 0;
        __syncthreads();
        sm[tid] += v;
        __syncthreads();
    }
    int offs = (tid > 0) ? sm[tid - 1] : 0;
#pragma unroll
    for (int t = 0; t < 16; t++) {
        int rp = offs + loc[t];
        g_rowptr[base + t] = rp;
        g_cursor[base + t] = rp;
    }
    if (tid == 1023) g_rowptr[N_HITS] = sm[1023];
}

__global__ void scatter_kernel(const int* __restrict__ dst) {
    int e = blockIdx.x * blockDim.x + threadIdx.x;
    if (e < N_EDGES) {
        int p = atomicAdd(&g_cursor[dst[e]], 1);
        g_esorted[p] = e;
    }
}

// ---------------- embed: h = x @ W(25x128) + b ----------------
__global__ __launch_bounds__(128) void embed_kernel(const float* __restrict__ x,
                                                    const float* __restrict__ W,
                                                    const float* __restrict__ b) {
    __shared__ float Ws[25 * HID];
    __shared__ float xs[16 * 25];
    int tid = threadIdx.x;
    for (int i = tid; i < 25 * HID; i += 128) Ws[i] = W[i];
    int rowBase = blockIdx.x * 16;
    for (int i = tid; i < 16 * 25; i += 128) xs[i] = x[(size_t)rowBase * 25 + i];
    __syncthreads();
    float bb = b[tid];
    for (int r = 0; r < 16; r++) {
        float acc = bb;
#pragma unroll
        for (int c = 0; c < 25; c++) acc += xs[r * 25 + c] * Ws[c * HID + tid];
        g_h[(size_t)(rowBase + r) * HID + tid] = acc;
    }
}

// ---------------- tensor-core GEMM on pre-packed bf16 hi/lo ----------
// A packed: [M][K] u32 (hi at [r][kp], lo at [r][K/2+kp]).
// B packed: Bh/Bl [N][K/2] u32 (pairs along K).
// grid = (N/64, M/128), block = 256 (8 warps, warp tile 32x32). K % 32 == 0.
// mode: 0 = fp32 out, 1 = fp32+relu, 2 = packed+relu (row stride N u32)
#define AST 20
#define BST 20

__global__ __launch_bounds__(256) void gemm_pk(const uint32_t* __restrict__ Apk,
                                               const uint32_t* __restrict__ Bh,
                                               const uint32_t* __restrict__ Bl,
                                               const float* __restrict__ bias,
                                               float* __restrict__ Cf,
                                               uint32_t* __restrict__ Cpk,
                                               int K, int N, int mode) {
    __shared__ uint32_t Ahs[128 * AST], Als[128 * AST];
    __shared__ uint32_t Bhs[64 * BST],  Bls[64 * BST];
    int K2 = K >> 1;
    int tid  = threadIdx.x;
    int lane = tid & 31, warp = tid >> 5;
    int wm = (warp & 3) * 32;       // M offset of warp tile
    int wn = (warp >> 2) * 32;      // N offset of warp tile
    int g = lane >> 2, t4 = lane & 3;
    int rowBase = blockIdx.y * 128, colBase = blockIdx.x * 64;

    float acc[2][4][4];
#pragma unroll
    for (int mf = 0; mf < 2; mf++)
#pragma unroll
        for (int nf = 0; nf < 4; nf++)
#pragma unroll
            for (int q = 0; q < 4; q++) acc[mf][nf][q] = 0.f;

    int bn_ = tid >> 2, bq = tid & 3;

    for (int kc2 = 0; kc2 < K2; kc2 += 16) {
        // stage A: 128 rows x 16 u32 hi + lo (uint4 vectors)
#pragma unroll
        for (int p = 0; p < 2; p++) {
            int idx = p * 256 + tid;
            int r = idx >> 2, q = idx & 3;
            const uint32_t* s = &Apk[(size_t)(rowBase + r) * K + kc2 + q * 4];
            *(uint4*)&Ahs[r * AST + q * 4] = *(const uint4*)s;
            *(uint4*)&Als[r * AST + q * 4] = *(const uint4*)(s + K2);
        }
        // stage B: 64 rows x 16 u32 hi + lo
        {
            const uint32_t* sh = &Bh[(size_t)(colBase + bn_) * K2 + kc2 + bq * 4];
            const uint32_t* sl = &Bl[(size_t)(colBase + bn_) * K2 + kc2 + bq * 4];
            *(uint4*)&Bhs[bn_ * BST + bq * 4] = *(const uint4*)sh;
            *(uint4*)&Bls[bn_ * BST + bq * 4] = *(const uint4*)sl;
        }
        __syncthreads();

#pragma unroll
        for (int ks = 0; ks < 2; ks++) {
            uint32_t ah[2][4], al[2][4], bh[4][2], bl[4][2];
            int ci = ks * 8 + t4;
#pragma unroll
            for (int mf = 0; mf < 2; mf++) {
                int r0 = (wm + mf * 16 + g) * AST;
                ah[mf][0] = Ahs[r0 + ci];           ah[mf][1] = Ahs[r0 + 8 * AST + ci];
                ah[mf][2] = Ahs[r0 + ci + 4];       ah[mf][3] = Ahs[r0 + 8 * AST + ci + 4];
                al[mf][0] = Als[r0 + ci];           al[mf][1] = Als[r0 + 8 * AST + ci];
                al[mf][2] = Als[r0 + ci + 4];       al[mf][3] = Als[r0 + 8 * AST + ci + 4];
            }
#pragma unroll
            for (int nf = 0; nf < 4; nf++) {
                int c0 = (wn + nf * 8 + g) * BST;
                bh[nf][0] = Bhs[c0 + ci];  bh[nf][1] = Bhs[c0 + ci + 4];
                bl[nf][0] = Bls[c0 + ci];  bl[nf][1] = Bls[c0 + ci + 4];
            }
#pragma unroll
            for (int mf = 0; mf < 2; mf++)
#pragma unroll
                for (int nf = 0; nf < 4; nf++) mma16816(acc[mf][nf], ah[mf], bh[nf]);
#pragma unroll
            for (int mf = 0; mf < 2; mf++)
#pragma unroll
                for (int nf = 0; nf < 4; nf++) mma16816(acc[mf][nf], al[mf], bh[nf]);
#pragma unroll
            for (int mf = 0; mf < 2; mf++)
#pragma unroll
                for (int nf = 0; nf < 4; nf++) mma16816(acc[mf][nf], ah[mf], bl[nf]);
        }
        __syncthreads();
    }

    // epilogue
#pragma unroll
    for (int mf = 0; mf < 2; mf++) {
#pragma unroll
        for (int nf = 0; nf < 4; nf++) {
            int row0 = rowBase + wm + mf * 16 + g;
            int col  = colBase + wn + nf * 8 + 2 * t4;
            float bx = bias ? bias[col] : 0.f;
            float by = bias ? bias[col + 1] : 0.f;
            float v0 = acc[mf][nf][0] + bx, v1 = acc[mf][nf][1] + by;
            float v2 = acc[mf][nf][2] + bx, v3 = acc[mf][nf][3] + by;
            if (mode >= 1) {
                v0 = fmaxf(v0, 0.f); v1 = fmaxf(v1, 0.f);
                v2 = fmaxf(v2, 0.f); v3 = fmaxf(v3, 0.f);
            }
            if (mode == 2) {
                int cp = col >> 1, N2 = N >> 1;
                uint32_t lo0, lo1;
                uint32_t hi0 = bf2_hi_lo(v0, v1, lo0);
                uint32_t hi1 = bf2_hi_lo(v2, v3, lo1);
                Cpk[(size_t)row0 * N + cp]            = hi0;
                Cpk[(size_t)row0 * N + N2 + cp]       = lo0;
                Cpk[(size_t)(row0 + 8) * N + cp]      = hi1;
                Cpk[(size_t)(row0 + 8) * N + N2 + cp] = lo1;
            } else {
                float2 o0; o0.x = v0; o0.y = v1;
                float2 o1; o1.x = v2; o1.y = v3;
                *(float2*)&Cf[(size_t)row0 * N + col]       = o0;
                *(float2*)&Cf[(size_t)(row0 + 8) * N + col] = o1;
            }
        }
    }
}

// ---------------- attention: one warp per node, CSR gather + online softmax ------------
// writes packed bf16 hi/lo output directly (consumed only by Wo GEMM)
__global__ __launch_bounds__(256) void attn_kernel(const float* __restrict__ qkv,
                                                   const int* __restrict__ src_idx,
                                                   const float* __restrict__ edge_attr,
                                                   const float* __restrict__ We,
                                                   const float* __restrict__ be) {
    __shared__ float4 We_s[5][32];
    __shared__ float4 be_s[32];
    int tid = threadIdx.x;
    if (tid < 160) { int c = tid >> 5, l = tid & 31; We_s[c][l] = *(const float4*)&We[c * HID + l * 4]; }
    if (tid < 32) be_s[tid] = *(const float4*)&be[tid * 4];
    __syncthreads();
    int lane = tid & 31;
    int node = blockIdx.x * 8 + (tid >> 5);
    if (node >= N_HITS) return;

    float4 q4 = *(const float4*)&qkv[(size_t)node * 384 + lane * 4];
    int p0 = g_rowptr[node], p1 = g_rowptr[node + 1];
    float m = -INFINITY, s = 0.f;
    float ax = 0.f, ay = 0.f, az = 0.f, aw = 0.f;
    float4 be4 = be_s[lane];
    float4 w0 = We_s[0][lane], w1 = We_s[1][lane], w2 = We_s[2][lane],
           w3 = We_s[3][lane], w4 = We_s[4][lane];

    for (int j = p0; j < p1; j++) {
        int eid = g_esorted[j];
        int sn = src_idx[eid];
        const float* ea = edge_attr + (size_t)eid * 5;
        float c0 = ea[0], c1 = ea[1], c2 = ea[2], c3 = ea[3], c4 = ea[4];
        float ex = be4.x + c0 * w0.x + c1 * w1.x + c2 * w2.x + c3 * w3.x + c4 * w4.x;
        float ey = be4.y + c0 * w0.y + c1 * w1.y + c2 * w2.y + c3 * w3.y + c4 * w4.y;
        float ez = be4.z + c0 * w0.z + c1 * w1.z + c2 * w2.z + c3 * w3.z + c4 * w4.z;
        float ew = be4.w + c0 * w0.w + c1 * w1.w + c2 * w2.w + c3 * w3.w + c4 * w4.w;
        const float* kb = qkv + (size_t)sn * 384;
        float4 k4 = *(const float4*)&kb[HID + lane * 4];
        float4 v4 = *(const float4*)&kb[2 * HID + lane * 4];
        float kx = k4.x + ex, ky = k4.y + ey, kz = k4.z + ez, kw = k4.w + ew;
        float prod = q4.x * kx + q4.y * ky + q4.z * kz + q4.w * kw;
        prod += __shfl_xor_sync(0xffffffffu, prod, 1);
        prod += __shfl_xor_sync(0xffffffffu, prod, 2);
        prod += __shfl_xor_sync(0xffffffffu, prod, 4);
        float logit = prod * 0.17677669529663689f;  // 1/sqrt(32)
        float nm = fmaxf(m, logit);
        float corr = __expf(m - nm);
        float p = __expf(logit - nm);
        s = s * corr + p;
        ax = ax * corr + p * (v4.x + ex);
        ay = ay * corr + p * (v4.y + ey);
        az = az * corr + p * (v4.z + ez);
        aw = aw * corr + p * (v4.w + ew);
        m = nm;
    }
    float inv = 1.f / fmaxf(s, 1e-9f);
    float ox = ax * inv, oy = ay * inv, oz = az * inv, ow = aw * inv;
    uint32_t lo0, lo1;
    uint32_t hi0 = bf2_hi_lo(ox, oy, lo0);
    uint32_t hi1 = bf2_hi_lo(oz, ow, lo1);
    uint2 hv; hv.x = hi0; hv.y = hi1;
    uint2 lv; lv.x = lo0; lv.y = lo1;
    *(uint2*)&g_attnpk[(size_t)node * HID + 2 * lane]      = hv;
    *(uint2*)&g_attnpk[(size_t)node * HID + 64 + 2 * lane] = lv;
}

// ---------------- residual + LayerNorm (warp per row); also emits packed h ----------------
__global__ __launch_bounds__(256) void ln_res_kernel(float* __restrict__ h,
                                                     const float* __restrict__ delta,
                                                     const float* __restrict__ gamma,
                                                     const float* __restrict__ beta) {
    int lane = threadIdx.x & 31;
    int row = blockIdx.x * 8 + (threadIdx.x >> 5);
    float4 hv = *(const float4*)&h[(size_t)row * HID + lane * 4];
    float4 dv = *(const float4*)&delta[(size_t)row * HID + lane * 4];
    float vx = hv.x + dv.x, vy = hv.y + dv.y, vz = hv.z + dv.z, vw = hv.w + dv.w;
    float sum = vx + vy + vz + vw;
#pragma unroll
    for (int o = 16; o > 0; o >>= 1) sum += __shfl_xor_sync(0xffffffffu, sum, o);
    float mean = sum * (1.f / 128.f);
    float dx = vx - mean, dy = vy - mean, dz = vz - mean, dw = vw - mean;
    float ss = dx * dx + dy * dy + dz * dz + dw * dw;
#pragma unroll
    for (int o = 16; o > 0; o >>= 1) ss += __shfl_xor_sync(0xffffffffu, ss, o);
    float rstd = rsqrtf(ss * (1.f / 128.f) + 1e-5f);
    float4 gv = *(const float4*)&gamma[lane * 4];
    float4 bv = *(const float4*)&beta[lane * 4];
    float4 o4;
    o4.x = dx * rstd * gv.x + bv.x;
    o4.y = dy * rstd * gv.y + bv.y;
    o4.z = dz * rstd * gv.z + bv.z;
    o4.w = dw * rstd * gv.w + bv.w;
    *(float4*)&h[(size_t)row * HID + lane * 4] = o4;
    uint32_t lo0, lo1;
    uint32_t hi0 = bf2_hi_lo(o4.x, o4.y, lo0);
    uint32_t hi1 = bf2_hi_lo(o4.z, o4.w, lo1);
    uint2 hp; hp.x = hi0; hp.y = hi1;
    uint2 lp; lp.x = lo0; lp.y = lo1;
    *(uint2*)&g_hpk[(size_t)row * HID + 2 * lane]      = hp;
    *(uint2*)&g_hpk[(size_t)row * HID + 64 + 2 * lane] = lp;
}

// ---------------- group pooling (atomics) ----------------
__global__ void pool_kernel(const float* __restrict__ x, const int* __restrict__ grp,
                            const float* __restrict__ h) {
    int tid = threadIdx.x;
    int hit = blockIdx.x * 2 + (tid >> 7);
    int f = tid & 127;
    int g = grp[hit];
    float val = h[(size_t)hit * HID + f];
    unsigned u = __float_as_uint(val);
    unsigned enc = (u & 0x80000000u) ? ~u : (u | 0x80000000u);
    atomicMax(&g_gmax[g * HID + f], enc);
    int view = (int)x[(size_t)hit * 25 + 3];
    if (view == 0)      atomicAdd(&g_sum0[g * HID + f], val);
    else if (view == 1) atomicAdd(&g_sum1[g * HID + f], val);
    if (f == 0) {
        atomicAdd(&g_cnt[g], 1);
        if (view == 0)      atomicAdd(&g_cnt[N_GROUPS + g], 1);
        else if (view == 1) atomicAdd(&g_cnt[2 * N_GROUPS + g], 1);
    }
}

__global__ void ge_kernel() {
    int g = blockIdx.x, f = threadIdx.x;
    float cA = (float)g_cnt[g];
    float c0 = (float)g_cnt[N_GROUPS + g];
    float c1 = (float)g_cnt[2 * N_GROUPS + g];
    float s0 = g_sum0[g * HID + f], s1 = g_sum1[g * HID + f];
    float px = s0 / fmaxf(c0, 1.f), py = s1 / fmaxf(c1, 1.f);
    float hx = (c0 > 0.f) ? 1.f : 0.f, hy = (c1 > 0.f) ? 1.f : 0.f;
    float sum_feat = px * hx + py * hy;
    float valid = fmaxf(hx + hy, 1.f);
    g_ge[g * 256 + f] = sum_feat / valid;
    unsigned u = g_gmax[g * HID + f];
    float gm = 0.f;
    if (cA > 0.f) {
        unsigned bits = (u & 0x80000000u) ? (u & 0x7fffffffu) : ~u;
        gm = __uint_as_float(bits);
    }
    g_ge[g * 256 + HID + f] = gm;
}

// ---------------- pairwise affinity scores ----------------
__global__ void scores_kernel(const float* __restrict__ W2v, const float* __restrict__ b2v) {
    __shared__ float sA[16][129];
    __shared__ float sB[16][129];
    __shared__ float w2s[HID];
    int tx = threadIdx.x, ty = threadIdx.y;
    int tid = ty * 16 + tx;
    int iBase = blockIdx.y * 16, jBase = blockIdx.x * 16;
#pragma unroll
    for (int q = 0; q < 2; q++) {
        int idx4 = tid * 2 + q;
        int r = idx4 >> 5;
        int c4 = (idx4 & 31) << 2;
        float4 a = *(const float4*)&g_Aff[(size_t)(iBase + r) * HID + c4];
        sA[r][c4] = a.x; sA[r][c4 + 1] = a.y; sA[r][c4 + 2] = a.z; sA[r][c4 + 3] = a.w;
        float4 b = *(const float4*)&g_Bff[(size_t)(jBase + r) * HID + c4];
        sB[r][c4] = b.x; sB[r][c4 + 1] = b.y; sB[r][c4 + 2] = b.z; sB[r][c4 + 3] = b.w;
    }
    if (tid < HID) w2s[tid] = W2v[tid];
    __syncthreads();
    float acc = b2v[0];
#pragma unroll 8
    for (int k = 0; k < HID; k++) {
        float t = sA[ty][k] + sB[tx][k];
        acc += fmaxf(t, 0.f) * w2s[k];
    }
    g_S[(size_t)(iBase + ty) * N_GROUPS + jBase + tx] = acc;
}

__global__ void final_kernel(const int* __restrict__ batch, float* __restrict__ out) {
    int idx = blockIdx.x * blockDim.x + threadIdx.x;
    if (idx >= N_GROUPS * N_GROUPS) return;
    int i = idx >> 9, j = idx & 511;
    float sc = 0.5f * (g_S[(size_t)i * N_GROUPS + j] + g_S[(size_t)j * N_GROUPS + i]);
    float p = 1.f / (1.f + expf(-sc));
    out[idx] = (batch[i] == batch[j]) ? p : 0.f;
}

// ---------------- host launcher ----------------
extern "C" void kernel_launch(void* const* d_in, const int* in_sizes, int n_in,
                              void* d_out, int out_size) {
    const float* x         = (const float*)d_in[0];
    const int*   ei        = (const int*)d_in[1];      // [2, E]: src then dst
    const float* edge_attr = (const float*)d_in[2];
    const int*   grp       = (const int*)d_in[3];
    const int*   batch     = (const int*)d_in[4];
    const float* embed_W   = (const float*)d_in[5];
    const float* embed_b   = (const float*)d_in[6];
    const float* Wqkv      = (const float*)d_in[7];
    const float* bqkv      = (const float*)d_in[8];
    const float* We        = (const float*)d_in[9];
    const float* be        = (const float*)d_in[10];
    const float* Wo        = (const float*)d_in[11];
    const float* bo        = (const float*)d_in[12];
    const float* ln1g      = (const float*)d_in[13];
    const float* ln1b      = (const float*)d_in[14];
    const float* W1        = (const float*)d_in[15];
    const float* b1        = (const float*)d_in[16];
    const float* W2        = (const float*)d_in[17];
    const float* b2        = (const float*)d_in[18];
    const float* ln2g      = (const float*)d_in[19];
    const float* ln2b      = (const float*)d_in[20];
    const float* affW1     = (const float*)d_in[21];
    const float* affb1     = (const float*)d_in[22];
    const float* affW2     = (const float*)d_in[23];
    const float* affb2     = (const float*)d_in[24];
    float* out = (float*)d_out;

    const int* dst = ei + N_EDGES;

    float *h, *qkv, *tmp, *ge, *Abuf, *Bbuf;
    uint32_t *hpk, *attnpk, *tmppk, *gepk, *wpk;
    cudaGetSymbolAddress((void**)&h,      g_h);
    cudaGetSymbolAddress((void**)&qkv,    g_qkv);
    cudaGetSymbolAddress((void**)&tmp,    g_tmp);
    cudaGetSymbolAddress((void**)&ge,     g_ge);
    cudaGetSymbolAddress((void**)&Abuf,   g_Aff);
    cudaGetSymbolAddress((void**)&Bbuf,   g_Bff);
    cudaGetSymbolAddress((void**)&hpk,    g_hpk);
    cudaGetSymbolAddress((void**)&attnpk, g_attnpk);
    cudaGetSymbolAddress((void**)&tmppk,  g_tmppk);
    cudaGetSymbolAddress((void**)&gepk,   g_gepk);
    cudaGetSymbolAddress((void**)&wpk,    g_wpk);

    // init + CSR (edge_index is layer-invariant: build once per launch)
    zero_kernel<<<128, 256>>>();
    hist_kernel<<<N_EDGES / 256, 256>>>(dst);
    scan_kernel<<<1, 1024>>>();
    scatter_kernel<<<N_EDGES / 256, 256>>>(dst);

    // one-time weight packing (bf16 hi/lo, pre-transposed)
    pack_weights<<<1280, 256>>>(Wqkv, Wo, W1, W2, affW1);

    // embed + pack h
    embed_kernel<<<N_HITS / 16, 128>>>(x, embed_W, embed_b);
    pack_rows<<<(N_HITS * 64) / 256, 256>>>(h, hpk, HID, N_HITS * 64);

    for (int l = 0; l < NLAYERS; l++) {
        const uint32_t* wb = wpk + (size_t)l * WL_STRIDE;
        // qkv = h @ Wqkv[l] + bqkv[l]   (16384 x 128 x 384)
        gemm_pk<<<dim3(6, N_HITS / 128), 256>>>(
            hpk, wb, wb + 24576, bqkv + (size_t)l * 384, qkv, nullptr, HID, 384, 0);
        // edge attention -> packed attn
        attn_kernel<<<N_HITS / 8, 256>>>(qkv, ei, edge_attr,
                                         We + (size_t)l * 5 * HID, be + (size_t)l * HID);
        // wo_out = attn @ Wo + bo
        gemm_pk<<<dim3(2, N_HITS / 128), 256>>>(
            attnpk, wb + 49152, wb + 57344, bo + (size_t)l * HID, tmp, nullptr, HID, HID, 0);
        // h = LN(h + wo_out)  (+ packed h)
        ln_res_kernel<<<N_HITS / 8, 256>>>(h, tmp, ln1g + (size_t)l * HID, ln1b + (size_t)l * HID);
        // hidden = relu(h @ W1 + b1) -> packed only
        gemm_pk<<<dim3(8, N_HITS / 128), 256>>>(
            hpk, wb + 65536, wb + 98304, b1 + (size_t)l * FFN_DIM, nullptr, tmppk, HID, FFN_DIM, 2);
        // ffn_out = hidden @ W2 + b2
        gemm_pk<<<dim3(2, N_HITS / 128), 256>>>(
            tmppk, wb + 131072, wb + 163840, b2 + (size_t)l * HID, tmp, nullptr, FFN_DIM, HID, 0);
        // h = LN(h + ffn_out)  (+ packed h)
        ln_res_kernel<<<N_HITS / 8, 256>>>(h, tmp, ln2g + (size_t)l * HID, ln2b + (size_t)l * HID);
    }

    // group pooling + ge features
    pool_kernel<<<N_HITS / 2, 256>>>(x, grp, h);
    ge_kernel<<<N_GROUPS, HID>>>();
    pack_rows<<<(N_GROUPS * 128) / 256, 256>>>(ge, gepk, 2 * HID, N_GROUPS * 128);

    // A = ge @ W1a + b1 ; B = ge @ W1b    (512 x 256 x 128)
    gemm_pk<<<dim3(2, N_GROUPS / 128), 256>>>(
        gepk, wpk + W_AFF, wpk + W_AFF + 16384, affb1, Abuf, nullptr, 2 * HID, HID, 0);
    gemm_pk<<<dim3(2, N_GROUPS / 128), 256>>>(
        gepk, wpk + W_AFF + 32768, wpk + W_AFF + 49152, nullptr, Bbuf, nullptr, 2 * HID, HID, 0);

    // pairwise scores + symmetrize + sigmoid + event mask
    scores_kernel<<<dim3(N_GROUPS / 16, N_GROUPS / 16), dim3(16, 16)>>>(affW2, affb2);
    final_kernel<<<(N_GROUPS * N_GROUPS) / 256, 256>>>(batch, out);

    (void)in_sizes; (void)n_in; (void)out_size;
}